// round 10
// baseline (speedup 1.0000x reference)
#include <cuda_runtime.h>
#include <cuda_fp16.h>
#include <cstdint>

#define KDIM 4096
#define NDIM 11008
#define MDIM 8192
#define NGROUPS 32
#define BM 128
#define BN 128
#define BK 64
#define PADH 8
#define LDSS (BK + PADH)         // 72 halves = 144B per A smem row
#define THREADS 256
#define KT (KDIM / BK)           // 64
#define ASTAGES 3

#define X_ELEMS   33554432
#define WP_ELEMS  22544384
#define SC_ELEMS  352256

#define A_STAGE_BYTES (BM * LDSS * 2)        // 18432
#define SMEM_BYTES (ASTAGES * A_STAGE_BYTES) // 55296

__device__ int g_is_f32;
__device__ __align__(16) __half  g_xh[(size_t)MDIM * KDIM];            // X as f16
__device__ __align__(16) __half  g_sch[SC_ELEMS];                      // scales as f16
__device__ __align__(16) uint8_t g_wr[(size_t)(NDIM / 8) * KT * 32 * 8]; // fragment-ordered W

// -------- detect dtype AND normalize scales to f16 --------
__global__ void detect_scales_kernel(const uint32_t* __restrict__ sc) {
    __shared__ int red[256];
    int c = 0;
    for (int i = threadIdx.x; i < 4096; i += 256) {
        float a = fabsf(__uint_as_float(sc[i]));
        if (a >= 1e-6f && a <= 4.0f) c++;
    }
    red[threadIdx.x] = c;
    __syncthreads();
    for (int s = 128; s > 0; s >>= 1) {
        if (threadIdx.x < s) red[threadIdx.x] += red[threadIdx.x + s];
        __syncthreads();
    }
    const int is_f32 = (red[0] > 2048) ? 1 : 0;
    if (threadIdx.x == 0) g_is_f32 = is_f32;

    if (is_f32) {
        const float* s4 = (const float*)sc;
        for (int i = threadIdx.x; i < SC_ELEMS; i += 256)
            g_sch[i] = __float2half_rn(s4[i]);
    } else {
        const __half* s2 = (const __half*)sc;
        for (int i = threadIdx.x; i < SC_ELEMS; i += 256)
            g_sch[i] = s2[i];
    }
}

// -------- normalize X to f16 --------
__global__ void convert_x_kernel(const void* __restrict__ Xraw) {
    size_t i = ((size_t)blockIdx.x * 256 + threadIdx.x) * 8;
    if (g_is_f32) {
        const float* Xf = (const float*)Xraw;
        float4 f0 = *(const float4*)(Xf + i);
        float4 f1 = *(const float4*)(Xf + i + 4);
        __half2 h0 = __floats2half2_rn(f0.x, f0.y);
        __half2 h1 = __floats2half2_rn(f0.z, f0.w);
        __half2 h2 = __floats2half2_rn(f1.x, f1.y);
        __half2 h3 = __floats2half2_rn(f1.z, f1.w);
        uint4 o;
        o.x = *(uint32_t*)&h0; o.y = *(uint32_t*)&h1;
        o.z = *(uint32_t*)&h2; o.w = *(uint32_t*)&h3;
        *(uint4*)(g_xh + i) = o;
    } else {
        *(uint4*)(g_xh + i) = *(const uint4*)((const __half*)Xraw + i);
    }
}

// -------- W repack into m16n8k16 B-fragment order --------
// g_wr[(((n8*64 + kt)*32) + lane)*8 + (kk*2 + reg)] =
//   payload byte WP[n8*8 + (lane>>2)][kt*32 + kk*8 + (lane&3) + reg*4]
// PTX B fragment: col n = lane>>2, k = (lane%4)*2 (+8 for reg1); byte = k/2 index.
__global__ void repack_w_kernel(const int* __restrict__ WP) {
    const int w    = blockIdx.x * 8 + (threadIdx.x >> 5);   // (n8,kt) id
    const int lane = threadIdx.x & 31;
    const int n8 = w >> 6, kt = w & 63;
    const int* src = WP + (size_t)(n8 * 8 + (lane >> 2)) * (KDIM / 2) + kt * 32 + (lane & 3);
    uint32_t lo = (src[0]  & 0xFF) | ((src[4]  & 0xFF) << 8) |
                  ((src[8]  & 0xFF) << 16) | ((src[12] & 0xFF) << 24);
    uint32_t hi = (src[16] & 0xFF) | ((src[20] & 0xFF) << 8) |
                  ((src[24] & 0xFF) << 16) | ((src[28] & 0xFF) << 24);
    uint2 o; o.x = lo; o.y = hi;
    *(uint2*)(g_wr + ((size_t)w * 32 + lane) * 8) = o;
}

// ---------------- helpers ----------------
__device__ __forceinline__ uint32_t smem_u32(const void* p) {
    return (uint32_t)__cvta_generic_to_shared(p);
}

__device__ __forceinline__ void ldsm_x4(uint32_t& r0, uint32_t& r1, uint32_t& r2, uint32_t& r3,
                                        uint32_t addr) {
    asm volatile("ldmatrix.sync.aligned.m8n8.x4.shared.b16 {%0,%1,%2,%3}, [%4];"
                 : "=r"(r0), "=r"(r1), "=r"(r2), "=r"(r3) : "r"(addr));
}

__device__ __forceinline__ void mma16816(float* c, const uint32_t* a, const uint32_t* b) {
    asm volatile("mma.sync.aligned.m16n8k16.row.col.f32.f16.f16.f32 "
                 "{%0,%1,%2,%3}, {%4,%5,%6,%7}, {%8,%9}, {%0,%1,%2,%3};"
                 : "+f"(c[0]), "+f"(c[1]), "+f"(c[2]), "+f"(c[3])
                 : "r"(a[0]), "r"(a[1]), "r"(a[2]), "r"(a[3]), "r"(b[0]), "r"(b[1]));
}

// dequant one byte (2 nibbles, low = even k) -> scaled half2 (fp16 math = reference)
__device__ __forceinline__ uint32_t dq2(uint32_t v, __half2 s2) {
    __half lo = __int2half_rn((int)(v & 0xF) - 8);
    __half hi = __int2half_rn((int)((v >> 4) & 0xF) - 8);
    __half2 p = __hmul2(__halves2half2(lo, hi), s2);
    return *reinterpret_cast<uint32_t*>(&p);
}

// ---------------- main GEMM: cp.async A (padded layout) + fragment-direct B ----
__global__ void __launch_bounds__(THREADS, 2)
w4a16_gemm(void* __restrict__ OUTv)
{
    extern __shared__ __half smem[];
    const uint32_t sb = smem_u32(smem);

    const int t  = threadIdx.x, lane = t & 31, wid = t >> 5;
    const int m0 = blockIdx.y * BM;
    const int n0 = blockIdx.x * BN;
    const int wm = (wid >> 2) * 64;
    const int wn = (wid & 3) * 32;

    // ---- A loader: 2 threads/row, 64B each via cp.async (padded dest = validated layout) ----
    const int rr = t >> 1, hf = t & 1;
    const __half* aSrc = g_xh + (size_t)(m0 + rr) * KDIM + hf * 32;
    const uint32_t aDst = rr * (LDSS * 2) + hf * 64;   // byte offset within stage

    // ---- B fragment source + scales ----
    const uint8_t* bBase = g_wr + ((size_t)((n0 >> 3) + (wn >> 3)) * KT * 32 + lane) * 8;
    const __half*  sBase = g_sch + (size_t)(n0 + wn + (lane >> 2)) * NGROUPS;

    float acc[4][4][4];
#pragma unroll
    for (int mi = 0; mi < 4; ++mi)
#pragma unroll
        for (int ni = 0; ni < 4; ++ni)
#pragma unroll
            for (int i = 0; i < 4; ++i) acc[mi][ni][i] = 0.0f;

    auto issueA = [&](int kt) {
        const uint32_t ad = sb + (kt % ASTAGES) * A_STAGE_BYTES + aDst;
        const __half* ap = aSrc + kt * BK;
#pragma unroll
        for (int j = 0; j < 4; ++j) {
            asm volatile("cp.async.cg.shared.global [%0], [%1], 16;"
                         :: "r"(ad + j * 16), "l"(ap + j * 8) : "memory");
        }
        asm volatile("cp.async.commit_group;" ::: "memory");
    };

    uint2 bb_cur[4], bb_nxt[4];
    uint32_t s2_cur[4], s2_nxt[4];

    auto loadB = [&](int kt, uint2* bb) {
#pragma unroll
        for (int ni = 0; ni < 4; ++ni)
            bb[ni] = *(const uint2*)(bBase + (size_t)ni * (KT * 32 * 8) + kt * 256);
    };
    auto loadS = [&](int g, uint32_t* s2) {
#pragma unroll
        for (int ni = 0; ni < 4; ++ni) {
            __half sh = __ldg(sBase + (size_t)ni * 8 * NGROUPS + g);
            __half2 s2h = __half2half2(sh);
            s2[ni] = *(uint32_t*)&s2h;
        }
    };

    // ---- prologue: A stages 0,1 in flight; B/scales for kt=0 resident ----
    issueA(0);
    issueA(1);
    loadB(0, bb_cur);
    loadS(0, s2_cur);

    const uint32_t aRowOff = (uint32_t)(wm + (lane & 15)) * (LDSS * 2) + (lane >> 4) * 16;

    for (int kt = 0; kt < KT; ++kt) {
        // stage kt ready (<=1 outstanding: stage kt+1)
        asm volatile("cp.async.wait_group 1;" ::: "memory");
        __syncthreads();                         // all warps past compute(kt-1), stage kt visible

        if (kt + 2 < KT) issueA(kt + 2);         // overwrites stage (kt-1)%3 — safe post-barrier
        const int ktn = (kt + 1) & (KT - 1);
        loadB(ktn, bb_nxt);
        loadS(ktn >> 1, s2_nxt);

        const uint32_t aBase = sb + (kt % ASTAGES) * A_STAGE_BYTES;
#pragma unroll
        for (int kk = 0; kk < 4; ++kk) {
            uint32_t a[4][4];
#pragma unroll
            for (int mi = 0; mi < 4; ++mi) {
                uint32_t addr = aBase + aRowOff + mi * 16 * (LDSS * 2) + kk * 32;
                ldsm_x4(a[mi][0], a[mi][1], a[mi][2], a[mi][3], addr);
            }
#pragma unroll
            for (int ni = 0; ni < 4; ++ni) {
                const uint32_t word = (kk < 2) ? bb_cur[ni].x : bb_cur[ni].y;
                const uint32_t sh = (kk & 1) * 16;
                __half2 s2h = *(__half2*)&s2_cur[ni];
                uint32_t b[2];
                b[0] = dq2((word >> sh) & 0xFF, s2h);        // k = kk*16 + (lane%4)*2
                b[1] = dq2((word >> (sh + 8)) & 0xFF, s2h);  // k = kk*16 + 8 + (lane%4)*2
#pragma unroll
                for (int mi = 0; mi < 4; ++mi)
                    mma16816(acc[mi][ni], a[mi], b);
            }
        }
#pragma unroll
        for (int ni = 0; ni < 4; ++ni) { bb_cur[ni] = bb_nxt[ni]; s2_cur[ni] = s2_nxt[ni]; }
    }

    // -------- epilogue --------
    const int gid  = lane >> 2;
    const int tid4 = lane & 3;
    const bool f32out = (g_is_f32 != 0);
#pragma unroll
    for (int mi = 0; mi < 4; ++mi) {
#pragma unroll
        for (int ni = 0; ni < 4; ++ni) {
            const int row0 = m0 + wm + mi * 16 + gid;
            const int col  = n0 + wn + ni * 8 + tid4 * 2;
            if (f32out) {
                float* OUT = (float*)OUTv;
                float v0 = __half2float(__float2half_rn(acc[mi][ni][0]));
                float v1 = __half2float(__float2half_rn(acc[mi][ni][1]));
                float v2 = __half2float(__float2half_rn(acc[mi][ni][2]));
                float v3 = __half2float(__float2half_rn(acc[mi][ni][3]));
                *(float2*)(OUT + (size_t)row0 * NDIM + col)       = make_float2(v0, v1);
                *(float2*)(OUT + (size_t)(row0 + 8) * NDIM + col) = make_float2(v2, v3);
            } else {
                __half* OUT = (__half*)OUTv;
                __half2 v0 = __floats2half2_rn(acc[mi][ni][0], acc[mi][ni][1]);
                __half2 v1 = __floats2half2_rn(acc[mi][ni][2], acc[mi][ni][3]);
                *(__half2*)(OUT + (size_t)row0 * NDIM + col)       = v0;
                *(__half2*)(OUT + (size_t)(row0 + 8) * NDIM + col) = v1;
            }
        }
    }
}

extern "C" void kernel_launch(void* const* d_in, const int* in_sizes, int n_in,
                              void* d_out, int out_size) {
    const void* X  = d_in[0];
    const int*  WP = (const int*)d_in[1];
    const void* SC = d_in[2];
    for (int i = 0; i < n_in; ++i) {
        if (in_sizes[i] == X_ELEMS)       X  = d_in[i];
        else if (in_sizes[i] == WP_ELEMS) WP = (const int*)d_in[i];
        else if (in_sizes[i] == SC_ELEMS) SC = d_in[i];
    }

    cudaFuncSetAttribute(w4a16_gemm,
                         cudaFuncAttributeMaxDynamicSharedMemorySize, SMEM_BYTES);

    detect_scales_kernel<<<1, 256>>>((const uint32_t*)SC);   // [0]
    convert_x_kernel<<<X_ELEMS / (256 * 8), 256>>>(X);       // [1]
    repack_w_kernel<<<NDIM, 256>>>(WP);                      // [2]

    dim3 grid(NDIM / BN, MDIM / BM);   // (86, 64)
    w4a16_gemm<<<grid, THREADS, SMEM_BYTES>>>(d_out);        // [3] profiled
}

// round 11
// speedup vs baseline: 1.0865x; 1.0865x over previous
#include <cuda_runtime.h>
#include <cuda_fp16.h>
#include <cstdint>

#define KDIM 4096
#define NDIM 11008
#define MDIM 8192
#define NGROUPS 32
#define BM 128
#define BN 128
#define BK 64
#define PADH 8
#define LDSS (BK + PADH)         // 72 halves = 144B per A smem row
#define THREADS 256
#define KT (KDIM / BK)           // 64
#define ASTAGES 3

#define X_ELEMS   33554432
#define WP_ELEMS  22544384
#define SC_ELEMS  352256

#define A_STAGE_BYTES (BM * LDSS * 2)        // 18432
#define SMEM_BYTES (ASTAGES * A_STAGE_BYTES) // 55296

__device__ int g_is_f32;
__device__ __align__(16) __half  g_xh[(size_t)MDIM * KDIM];              // X as f16
__device__ __align__(16) __half  g_sch[SC_ELEMS];                        // scales as f16
__device__ __align__(16) uint8_t g_wr[(size_t)(NDIM / 8) * KT * 32 * 8]; // fragment-ordered W

// -------- detect dtype AND normalize scales to f16 --------
__global__ void detect_scales_kernel(const uint32_t* __restrict__ sc) {
    __shared__ int red[256];
    int c = 0;
    for (int i = threadIdx.x; i < 4096; i += 256) {
        float a = fabsf(__uint_as_float(sc[i]));
        if (a >= 1e-6f && a <= 4.0f) c++;
    }
    red[threadIdx.x] = c;
    __syncthreads();
    for (int s = 128; s > 0; s >>= 1) {
        if (threadIdx.x < s) red[threadIdx.x] += red[threadIdx.x + s];
        __syncthreads();
    }
    const int is_f32 = (red[0] > 2048) ? 1 : 0;
    if (threadIdx.x == 0) g_is_f32 = is_f32;

    if (is_f32) {
        const float* s4 = (const float*)sc;
        for (int i = threadIdx.x; i < SC_ELEMS; i += 256)
            g_sch[i] = __float2half_rn(s4[i]);
    } else {
        const __half* s2 = (const __half*)sc;
        for (int i = threadIdx.x; i < SC_ELEMS; i += 256)
            g_sch[i] = s2[i];
    }
}

// -------- normalize X to f16 --------
__global__ void convert_x_kernel(const void* __restrict__ Xraw) {
    size_t i = ((size_t)blockIdx.x * 256 + threadIdx.x) * 8;
    if (g_is_f32) {
        const float* Xf = (const float*)Xraw;
        float4 f0 = *(const float4*)(Xf + i);
        float4 f1 = *(const float4*)(Xf + i + 4);
        __half2 h0 = __floats2half2_rn(f0.x, f0.y);
        __half2 h1 = __floats2half2_rn(f0.z, f0.w);
        __half2 h2 = __floats2half2_rn(f1.x, f1.y);
        __half2 h3 = __floats2half2_rn(f1.z, f1.w);
        uint4 o;
        o.x = *(uint32_t*)&h0; o.y = *(uint32_t*)&h1;
        o.z = *(uint32_t*)&h2; o.w = *(uint32_t*)&h3;
        *(uint4*)(g_xh + i) = o;
    } else {
        *(uint4*)(g_xh + i) = *(const uint4*)((const __half*)Xraw + i);
    }
}

// -------- W repack into m16n8k16 B-fragment order (validated in R9) --------
__global__ void repack_w_kernel(const int* __restrict__ WP) {
    const int w    = blockIdx.x * 8 + (threadIdx.x >> 5);   // (n8,kt) id
    const int lane = threadIdx.x & 31;
    const int n8 = w >> 6, kt = w & 63;
    const int* src = WP + (size_t)(n8 * 8 + (lane >> 2)) * (KDIM / 2) + kt * 32 + (lane & 3);
    uint32_t lo = (src[0]  & 0xFF) | ((src[4]  & 0xFF) << 8) |
                  ((src[8]  & 0xFF) << 16) | ((src[12] & 0xFF) << 24);
    uint32_t hi = (src[16] & 0xFF) | ((src[20] & 0xFF) << 8) |
                  ((src[24] & 0xFF) << 16) | ((src[28] & 0xFF) << 24);
    uint2 o; o.x = lo; o.y = hi;
    *(uint2*)(g_wr + ((size_t)w * 32 + lane) * 8) = o;
}

// ---------------- helpers ----------------
__device__ __forceinline__ uint32_t smem_u32(const void* p) {
    return (uint32_t)__cvta_generic_to_shared(p);
}

__device__ __forceinline__ void ldsm_x4(uint32_t& r0, uint32_t& r1, uint32_t& r2, uint32_t& r3,
                                        uint32_t addr) {
    asm volatile("ldmatrix.sync.aligned.m8n8.x4.shared.b16 {%0,%1,%2,%3}, [%4];"
                 : "=r"(r0), "=r"(r1), "=r"(r2), "=r"(r3) : "r"(addr));
}

__device__ __forceinline__ void mma16816(float* c, const uint32_t* a, const uint32_t* b) {
    asm volatile("mma.sync.aligned.m16n8k16.row.col.f32.f16.f16.f32 "
                 "{%0,%1,%2,%3}, {%4,%5,%6,%7}, {%8,%9}, {%0,%1,%2,%3};"
                 : "+f"(c[0]), "+f"(c[1]), "+f"(c[2]), "+f"(c[3])
                 : "r"(a[0]), "r"(a[1]), "r"(a[2]), "r"(a[3]), "r"(b[0]), "r"(b[1]));
}

// Fast dequant: v MUST be masked to low byte. Builds half2(1024+qlo, 1024+qhi),
// subtracts 1032 (exact: == q-8 in fp16), multiplies by scale (fp16 = reference).
// All fixed-latency ALU/FMA ops; no I2F.
__device__ __forceinline__ uint32_t dq2m(uint32_t v, uint32_t s2) {
    uint32_t tt = ((v | (v << 12)) & 0x000F000F) | 0x64006400;
    const uint32_t c1032 = 0x64086408;
    __half2 h = __hsub2(*(__half2*)&tt, *(const __half2*)&c1032);
    __half2 r = __hmul2(h, *(__half2*)&s2);
    return *(uint32_t*)&r;
}

// ---------------- main GEMM: cp.async A + fragment-direct B (fast dequant) ----
__global__ void __launch_bounds__(THREADS, 2)
w4a16_gemm(void* __restrict__ OUTv)
{
    extern __shared__ __half smem[];
    const uint32_t sb = smem_u32(smem);

    const int t  = threadIdx.x, lane = t & 31, wid = t >> 5;
    const int m0 = blockIdx.y * BM;
    const int n0 = blockIdx.x * BN;
    const int wm = (wid >> 2) * 64;
    const int wn = (wid & 3) * 32;

    // ---- A loader: 2 threads/row, 64B each via cp.async (padded dest) ----
    const int rr = t >> 1, hf = t & 1;
    const __half* aSrc = g_xh + (size_t)(m0 + rr) * KDIM + hf * 32;
    const uint32_t aDst = rr * (LDSS * 2) + hf * 64;

    // ---- B fragment source + scales ----
    const uint8_t* bBase = g_wr + ((size_t)((n0 >> 3) + (wn >> 3)) * KT * 32 + lane) * 8;
    const __half*  sBase = g_sch + (size_t)(n0 + wn + (lane >> 2)) * NGROUPS;

    float acc[4][4][4];
#pragma unroll
    for (int mi = 0; mi < 4; ++mi)
#pragma unroll
        for (int ni = 0; ni < 4; ++ni)
#pragma unroll
            for (int i = 0; i < 4; ++i) acc[mi][ni][i] = 0.0f;

    auto issueA = [&](int kt) {
        const uint32_t ad = sb + (kt % ASTAGES) * A_STAGE_BYTES + aDst;
        const __half* ap = aSrc + kt * BK;
#pragma unroll
        for (int j = 0; j < 4; ++j) {
            asm volatile("cp.async.cg.shared.global [%0], [%1], 16;"
                         :: "r"(ad + j * 16), "l"(ap + j * 8) : "memory");
        }
        asm volatile("cp.async.commit_group;" ::: "memory");
    };

    uint2 bb_cur[4], bb_nxt[4];
    uint32_t s2_cur[4], s2_nxt[4];

    auto loadB = [&](int kt, uint2* bb) {
#pragma unroll
        for (int ni = 0; ni < 4; ++ni)
            bb[ni] = *(const uint2*)(bBase + (size_t)ni * (KT * 32 * 8) + kt * 256);
    };
    auto loadS = [&](int g, uint32_t* s2) {
#pragma unroll
        for (int ni = 0; ni < 4; ++ni) {
            __half sh = __ldg(sBase + (size_t)ni * 8 * NGROUPS + g);
            __half2 s2h = __half2half2(sh);
            s2[ni] = *(uint32_t*)&s2h;
        }
    };

    // ---- prologue ----
    issueA(0);
    issueA(1);
    loadB(0, bb_cur);
    loadS(0, s2_cur);

    const uint32_t aRowOff = (uint32_t)(wm + (lane & 15)) * (LDSS * 2) + (lane >> 4) * 16;

    for (int kt = 0; kt < KT; ++kt) {
        asm volatile("cp.async.wait_group 1;" ::: "memory");
        __syncthreads();

        if (kt + 2 < KT) issueA(kt + 2);
        const int ktn = (kt + 1) & (KT - 1);
        loadB(ktn, bb_nxt);
        loadS(ktn >> 1, s2_nxt);

        const uint32_t aBase = sb + (kt % ASTAGES) * A_STAGE_BYTES;
#pragma unroll
        for (int kk = 0; kk < 4; ++kk) {
            uint32_t a[4][4];
#pragma unroll
            for (int mi = 0; mi < 4; ++mi) {
                uint32_t addr = aBase + aRowOff + mi * 16 * (LDSS * 2) + kk * 32;
                ldsm_x4(a[mi][0], a[mi][1], a[mi][2], a[mi][3], addr);
            }
#pragma unroll
            for (int ni = 0; ni < 4; ++ni) {
                const uint32_t word = (kk < 2) ? bb_cur[ni].x : bb_cur[ni].y;
                const uint32_t sh = (kk & 1) * 16;
                uint32_t b[2];
                b[0] = dq2m((word >> sh) & 0xFF, s2_cur[ni]);        // k = kk*16 + (lane%4)*2
                b[1] = dq2m((word >> (sh + 8)) & 0xFF, s2_cur[ni]);  // k = +8
#pragma unroll
                for (int mi = 0; mi < 4; ++mi)
                    mma16816(acc[mi][ni], a[mi], b);
            }
        }
#pragma unroll
        for (int ni = 0; ni < 4; ++ni) { bb_cur[ni] = bb_nxt[ni]; s2_cur[ni] = s2_nxt[ni]; }
    }

    // -------- epilogue --------
    const int gid  = lane >> 2;
    const int tid4 = lane & 3;
    const bool f32out = (g_is_f32 != 0);
#pragma unroll
    for (int mi = 0; mi < 4; ++mi) {
#pragma unroll
        for (int ni = 0; ni < 4; ++ni) {
            const int row0 = m0 + wm + mi * 16 + gid;
            const int col  = n0 + wn + ni * 8 + tid4 * 2;
            if (f32out) {
                float* OUT = (float*)OUTv;
                float v0 = __half2float(__float2half_rn(acc[mi][ni][0]));
                float v1 = __half2float(__float2half_rn(acc[mi][ni][1]));
                float v2 = __half2float(__float2half_rn(acc[mi][ni][2]));
                float v3 = __half2float(__float2half_rn(acc[mi][ni][3]));
                *(float2*)(OUT + (size_t)row0 * NDIM + col)       = make_float2(v0, v1);
                *(float2*)(OUT + (size_t)(row0 + 8) * NDIM + col) = make_float2(v2, v3);
            } else {
                __half* OUT = (__half*)OUTv;
                __half2 v0 = __floats2half2_rn(acc[mi][ni][0], acc[mi][ni][1]);
                __half2 v1 = __floats2half2_rn(acc[mi][ni][2], acc[mi][ni][3]);
                *(__half2*)(OUT + (size_t)row0 * NDIM + col)       = v0;
                *(__half2*)(OUT + (size_t)(row0 + 8) * NDIM + col) = v1;
            }
        }
    }
}

extern "C" void kernel_launch(void* const* d_in, const int* in_sizes, int n_in,
                              void* d_out, int out_size) {
    const void* X  = d_in[0];
    const int*  WP = (const int*)d_in[1];
    const void* SC = d_in[2];
    for (int i = 0; i < n_in; ++i) {
        if (in_sizes[i] == X_ELEMS)       X  = d_in[i];
        else if (in_sizes[i] == WP_ELEMS) WP = (const int*)d_in[i];
        else if (in_sizes[i] == SC_ELEMS) SC = d_in[i];
    }

    cudaFuncSetAttribute(w4a16_gemm,
                         cudaFuncAttributeMaxDynamicSharedMemorySize, SMEM_BYTES);

    detect_scales_kernel<<<1, 256>>>((const uint32_t*)SC);   // [0]
    convert_x_kernel<<<X_ELEMS / (256 * 8), 256>>>(X);       // [1]
    repack_w_kernel<<<NDIM, 256>>>(WP);                      // [2]

    dim3 grid(NDIM / BN, MDIM / BM);   // (86, 64)
    w4a16_gemm<<<grid, THREADS, SMEM_BYTES>>>(d_out);        // [3] profiled
}

// round 13
// speedup vs baseline: 1.0950x; 1.0078x over previous
#include <cuda_runtime.h>
#include <cuda_fp16.h>
#include <cstdint>

#define KDIM 4096
#define NDIM 11008
#define MDIM 8192
#define NGROUPS 32
#define BM 128
#define BN 128
#define BK 64
#define PADH 8
#define LDSS (BK + PADH)         // 72 halves = 144B per A smem row
#define THREADS 256
#define KT (KDIM / BK)           // 64
#define ASTAGES 4

#define X_ELEMS   33554432
#define WP_ELEMS  22544384
#define SC_ELEMS  352256

#define A_STAGE_BYTES (BM * LDSS * 2)        // 18432
#define SMEM_BYTES (ASTAGES * A_STAGE_BYTES) // 73728

__device__ int g_is_f32;
__device__ __align__(16) __half  g_xh[(size_t)MDIM * KDIM];              // X as f16
__device__ __align__(16) __half  g_sch[SC_ELEMS];                        // scales as f16
__device__ __align__(16) uint8_t g_wr[(size_t)(NDIM / 8) * KT * 32 * 8]; // fragment-ordered W

// -------- detect dtype AND normalize scales to f16 --------
__global__ void detect_scales_kernel(const uint32_t* __restrict__ sc) {
    __shared__ int red[256];
    int c = 0;
    for (int i = threadIdx.x; i < 4096; i += 256) {
        float a = fabsf(__uint_as_float(sc[i]));
        if (a >= 1e-6f && a <= 4.0f) c++;
    }
    red[threadIdx.x] = c;
    __syncthreads();
    for (int s = 128; s > 0; s >>= 1) {
        if (threadIdx.x < s) red[threadIdx.x] += red[threadIdx.x + s];
        __syncthreads();
    }
    const int is_f32 = (red[0] > 2048) ? 1 : 0;
    if (threadIdx.x == 0) g_is_f32 = is_f32;

    if (is_f32) {
        const float* s4 = (const float*)sc;
        for (int i = threadIdx.x; i < SC_ELEMS; i += 256)
            g_sch[i] = __float2half_rn(s4[i]);
    } else {
        const __half* s2 = (const __half*)sc;
        for (int i = threadIdx.x; i < SC_ELEMS; i += 256)
            g_sch[i] = s2[i];
    }
}

// -------- normalize X to f16 --------
__global__ void convert_x_kernel(const void* __restrict__ Xraw) {
    size_t i = ((size_t)blockIdx.x * 256 + threadIdx.x) * 8;
    if (g_is_f32) {
        const float* Xf = (const float*)Xraw;
        float4 f0 = *(const float4*)(Xf + i);
        float4 f1 = *(const float4*)(Xf + i + 4);
        __half2 h0 = __floats2half2_rn(f0.x, f0.y);
        __half2 h1 = __floats2half2_rn(f0.z, f0.w);
        __half2 h2 = __floats2half2_rn(f1.x, f1.y);
        __half2 h3 = __floats2half2_rn(f1.z, f1.w);
        uint4 o;
        o.x = *(uint32_t*)&h0; o.y = *(uint32_t*)&h1;
        o.z = *(uint32_t*)&h2; o.w = *(uint32_t*)&h3;
        *(uint4*)(g_xh + i) = o;
    } else {
        *(uint4*)(g_xh + i) = *(const uint4*)((const __half*)Xraw + i);
    }
}

// -------- W repack into m16n8k16 B-fragment order (validated) --------
__global__ void repack_w_kernel(const int* __restrict__ WP) {
    const int w    = blockIdx.x * 8 + (threadIdx.x >> 5);   // (n8,kt) id
    const int lane = threadIdx.x & 31;
    const int n8 = w >> 6, kt = w & 63;
    const int* src = WP + (size_t)(n8 * 8 + (lane >> 2)) * (KDIM / 2) + kt * 32 + (lane & 3);
    uint32_t lo = (src[0]  & 0xFF) | ((src[4]  & 0xFF) << 8) |
                  ((src[8]  & 0xFF) << 16) | ((src[12] & 0xFF) << 24);
    uint32_t hi = (src[16] & 0xFF) | ((src[20] & 0xFF) << 8) |
                  ((src[24] & 0xFF) << 16) | ((src[28] & 0xFF) << 24);
    uint2 o; o.x = lo; o.y = hi;
    *(uint2*)(g_wr + ((size_t)w * 32 + lane) * 8) = o;
}

// ---------------- helpers ----------------
__device__ __forceinline__ uint32_t smem_u32(const void* p) {
    return (uint32_t)__cvta_generic_to_shared(p);
}

__device__ __forceinline__ void ldsm_x4(uint32_t& r0, uint32_t& r1, uint32_t& r2, uint32_t& r3,
                                        uint32_t addr) {
    asm volatile("ldmatrix.sync.aligned.m8n8.x4.shared.b16 {%0,%1,%2,%3}, [%4];"
                 : "=r"(r0), "=r"(r1), "=r"(r2), "=r"(r3) : "r"(addr));
}

__device__ __forceinline__ void mma16816(float* c, const uint32_t* a, const uint32_t* b) {
    asm volatile("mma.sync.aligned.m16n8k16.row.col.f32.f16.f16.f32 "
                 "{%0,%1,%2,%3}, {%4,%5,%6,%7}, {%8,%9}, {%0,%1,%2,%3};"
                 : "+f"(c[0]), "+f"(c[1]), "+f"(c[2]), "+f"(c[3])
                 : "r"(a[0]), "r"(a[1]), "r"(a[2]), "r"(a[3]), "r"(b[0]), "r"(b[1]));
}

// Pair dequant: hw = 16-bit halfword holding bytes (b0, b1); produces the two
// scaled half2 B-registers. t = 1024+q built via magic 0x6400; (t-1032) == q-8
// exactly in fp16; then fp16 mul by scale (matches reference bit-for-bit).
__device__ __forceinline__ void dq_pair(uint32_t hw, uint32_t s2,
                                        uint32_t& b0, uint32_t& b1) {
    uint32_t t0 = ((hw | (hw << 12)) & 0x000F000F) | 0x64006400;
    uint32_t t1 = (((hw >> 8) | (hw << 4)) & 0x000F000F) | 0x64006400;
    const uint32_t c1032 = 0x64086408;
    __half2 h0 = __hsub2(*(__half2*)&t0, *(const __half2*)&c1032);
    __half2 h1 = __hsub2(*(__half2*)&t1, *(const __half2*)&c1032);
    __half2 r0 = __hmul2(h0, *(__half2*)&s2);
    __half2 r1 = __hmul2(h1, *(__half2*)&s2);
    b0 = *(uint32_t*)&r0;
    b1 = *(uint32_t*)&r1;
}

// ---------------- main GEMM ----------------
__global__ void __launch_bounds__(THREADS, 2)
w4a16_gemm(void* __restrict__ OUTv)
{
    extern __shared__ __half smem[];
    const uint32_t sb = smem_u32(smem);

    const int t  = threadIdx.x, lane = t & 31, wid = t >> 5;
    const int m0 = blockIdx.y * BM;
    const int n0 = blockIdx.x * BN;
    const int wm = (wid >> 2) * 64;
    const int wn = (wid & 3) * 32;

    // ---- A loader: 2 threads/row, 64B each via cp.async ----
    const int rr = t >> 1, hf = t & 1;
    const __half* aSrc = g_xh + (size_t)(m0 + rr) * KDIM + hf * 32;
    const uint32_t aDst = rr * (LDSS * 2) + hf * 64;

    // ---- B fragment source + scales ----
    const uint8_t* bBase = g_wr + ((size_t)((n0 >> 3) + (wn >> 3)) * KT * 32 + lane) * 8;
    const __half*  sBase = g_sch + (size_t)(n0 + wn + (lane >> 2)) * NGROUPS;

    float acc[4][4][4];
#pragma unroll
    for (int mi = 0; mi < 4; ++mi)
#pragma unroll
        for (int ni = 0; ni < 4; ++ni)
#pragma unroll
            for (int i = 0; i < 4; ++i) acc[mi][ni][i] = 0.0f;

    auto issueA = [&](int kt) {
        const uint32_t ad = sb + (kt & (ASTAGES - 1)) * A_STAGE_BYTES + aDst;
        const __half* ap = aSrc + kt * BK;
#pragma unroll
        for (int j = 0; j < 4; ++j) {
            asm volatile("cp.async.cg.shared.global [%0], [%1], 16;"
                         :: "r"(ad + j * 16), "l"(ap + j * 8) : "memory");
        }
        asm volatile("cp.async.commit_group;" ::: "memory");
    };

    uint2 bbA[4], bbB[4];
    uint32_t s2A[4], s2B[4];

    auto loadB = [&](int kt, uint2* bb) {
#pragma unroll
        for (int ni = 0; ni < 4; ++ni)
            bb[ni] = *(const uint2*)(bBase + (size_t)ni * (KT * 32 * 8) + kt * 256);
    };
    auto loadS = [&](int g, uint32_t* s2) {
#pragma unroll
        for (int ni = 0; ni < 4; ++ni) {
            __half sh = __ldg(sBase + (size_t)ni * 8 * NGROUPS + g);
            __half2 s2h = __half2half2(sh);
            s2[ni] = *(uint32_t*)&s2h;
        }
    };

    const uint32_t aRowOff = (uint32_t)(wm + (lane & 15)) * (LDSS * 2) + (lane >> 4) * 16;

    auto compute = [&](int kt, const uint2* bb, const uint32_t* s2) {
        const uint32_t aBase = sb + (kt & (ASTAGES - 1)) * A_STAGE_BYTES + aRowOff;
#pragma unroll
        for (int kk = 0; kk < 4; ++kk) {
            uint32_t a[4][4];
#pragma unroll
            for (int mi = 0; mi < 4; ++mi)
                ldsm_x4(a[mi][0], a[mi][1], a[mi][2], a[mi][3],
                        aBase + mi * 16 * (LDSS * 2) + kk * 32);
#pragma unroll
            for (int ni = 0; ni < 4; ++ni) {
                const uint32_t word = (kk < 2) ? bb[ni].x : bb[ni].y;
                const uint32_t hw = (kk & 1) ? (word >> 16) : (word & 0xFFFF);
                uint32_t b[2];
                dq_pair(hw, s2[ni], b[0], b[1]);
#pragma unroll
                for (int mi = 0; mi < 4; ++mi)
                    mma16816(acc[mi][ni], a[mi], b);
            }
        }
    };

    // ---- prologue: 3 A-stages in flight; B/scales for kt=0 resident ----
    issueA(0); issueA(1); issueA(2);
    loadB(0, bbA);
    loadS(0, s2A);

    // ---- mainloop, unrolled by 2 ----
    for (int kt2 = 0; kt2 < KT; kt2 += 2) {
        // -- kt2 (even): stage kt2 ready after wait (3 groups max in flight) --
        asm volatile("cp.async.wait_group 2;" ::: "memory");
        __syncthreads();
        if (kt2 + 3 < KT) issueA(kt2 + 3);
        loadB(kt2 + 1, bbB);
        loadS(((kt2 >> 1) + 1) & (NGROUPS - 1), s2B);   // scales for kt2+2, kt2+3
        compute(kt2, bbA, s2A);

        // -- kt2+1 (odd) --
        asm volatile("cp.async.wait_group 2;" ::: "memory");
        __syncthreads();
        if (kt2 + 4 < KT) issueA(kt2 + 4);
        loadB((kt2 + 2) & (KT - 1), bbA);
        compute(kt2 + 1, bbB, s2A);

#pragma unroll
        for (int ni = 0; ni < 4; ++ni) s2A[ni] = s2B[ni];
    }

    // -------- epilogue --------
    const int gid  = lane >> 2;
    const int tid4 = lane & 3;
    const bool f32out = (g_is_f32 != 0);
#pragma unroll
    for (int mi = 0; mi < 4; ++mi) {
#pragma unroll
        for (int ni = 0; ni < 4; ++ni) {
            const int row0 = m0 + wm + mi * 16 + gid;
            const int col  = n0 + wn + ni * 8 + tid4 * 2;
            if (f32out) {
                float* OUT = (float*)OUTv;
                float v0 = __half2float(__float2half_rn(acc[mi][ni][0]));
                float v1 = __half2float(__float2half_rn(acc[mi][ni][1]));
                float v2 = __half2float(__float2half_rn(acc[mi][ni][2]));
                float v3 = __half2float(__float2half_rn(acc[mi][ni][3]));
                *(float2*)(OUT + (size_t)row0 * NDIM + col)       = make_float2(v0, v1);
                *(float2*)(OUT + (size_t)(row0 + 8) * NDIM + col) = make_float2(v2, v3);
            } else {
                __half* OUT = (__half*)OUTv;
                __half2 v0 = __floats2half2_rn(acc[mi][ni][0], acc[mi][ni][1]);
                __half2 v1 = __floats2half2_rn(acc[mi][ni][2], acc[mi][ni][3]);
                *(__half2*)(OUT + (size_t)row0 * NDIM + col)       = v0;
                *(__half2*)(OUT + (size_t)(row0 + 8) * NDIM + col) = v1;
            }
        }
    }
}

extern "C" void kernel_launch(void* const* d_in, const int* in_sizes, int n_in,
                              void* d_out, int out_size) {
    const void* X  = d_in[0];
    const int*  WP = (const int*)d_in[1];
    const void* SC = d_in[2];
    for (int i = 0; i < n_in; ++i) {
        if (in_sizes[i] == X_ELEMS)       X  = d_in[i];
        else if (in_sizes[i] == WP_ELEMS) WP = (const int*)d_in[i];
        else if (in_sizes[i] == SC_ELEMS) SC = d_in[i];
    }

    cudaFuncSetAttribute(w4a16_gemm,
                         cudaFuncAttributeMaxDynamicSharedMemorySize, SMEM_BYTES);

    detect_scales_kernel<<<1, 256>>>((const uint32_t*)SC);   // [0]
    convert_x_kernel<<<X_ELEMS / (256 * 8), 256>>>(X);       // [1]
    repack_w_kernel<<<NDIM, 256>>>(WP);                      // [2]

    dim3 grid(NDIM / BN, MDIM / BM);   // (86, 64)
    w4a16_gemm<<<grid, THREADS, SMEM_BYTES>>>(d_out);        // [3] profiled
}